// round 13
// baseline (speedup 1.0000x reference)
#include <cuda_runtime.h>
#include <cstdint>

#define NN 4096
#define DD 128
#define EPSF 1e-12f
#define KS 8            // split-K factor for GEMMs (256 CTAs -> 2/SM)
#define BM 128          // GEMM block rows
#define BK 16           // GEMM k-tile
#define STAGES 4        // cp.async pipeline depth
#define AS_STRIDE 20    // floats; conflict-free for As[m][k] frag reads
#define BS_STRIDE 136   // floats; conflict-free for Bs[k][n] frag reads
#define AS_FLOATS (BM * AS_STRIDE)          // 2560
#define BS_FLOATS (BK * BS_STRIDE)          // 2176
#define SMEM_BYTES (STAGES * (AS_FLOATS + BS_FLOATS) * 4)   // 75776 B

// Scratch (static device allocation — no cudaMalloc allowed).
// RULE (cost of 3 failed rounds): __device__ symbols must NEVER be passed as
// kernel arguments from host code — host sees the shadow address, the kernel
// gets garbage, and the illegal access poisons the whole graph.
__device__ __align__(256) float g_att[(size_t)NN * NN];  // 64 MB dense att input
__device__ __align__(256) float g_feat[NN * DD];         // W @ activities (raw fp32)
__device__ __align__(256) float g_Bcvt[NN * DD];         // current B, tf32-rounded
__device__ __align__(256) float g_norm[NN];              // row sums of g_att
__device__ int g_is64;                                   // index dtype sniff

// ---------------------------------------------------------------------------
// Kernel 0: zero att + feat + norm, sniff int64 vs int32 indices.
// ---------------------------------------------------------------------------
__global__ void k_zero(const unsigned* __restrict__ cur_raw) {
    if (blockIdx.x == 0 && threadIdx.x == 0) {
        unsigned o = 0;
#pragma unroll
        for (int i = 1; i < 128; i += 2) o |= cur_raw[i];
        g_is64 = (o == 0) ? 1 : 0;
    }
    size_t idx    = (size_t)blockIdx.x * blockDim.x + threadIdx.x;
    size_t stride = (size_t)gridDim.x * blockDim.x;
    float4 z = make_float4(0.f, 0.f, 0.f, 0.f);
    float4* pa = (float4*)g_att;
    const size_t na = ((size_t)NN * NN) / 4;
    for (size_t i = idx; i < na; i += stride) pa[i] = z;
    float4* pf = (float4*)g_feat;
    const size_t nf = (size_t)(NN * DD) / 4;
    for (size_t i = idx; i < nf; i += stride) pf[i] = z;
    for (size_t i = idx; i < NN; i += stride) g_norm[i] = 0.f;
}

// ---------------------------------------------------------------------------
// Kernel 1: one warp per edge. dist = ||h + case - t||, val = exp(-dist),
// scatter into att[t][c] and accumulate row norm (linear => == row sums).
// ---------------------------------------------------------------------------
__global__ void k_edge(const void* __restrict__ curp, const void* __restrict__ tgtp,
                       const float* __restrict__ act, const float* __restrict__ cases,
                       int E) {
    int w = (int)((blockIdx.x * blockDim.x + threadIdx.x) >> 5);
    if (w >= E) return;
    int lane = threadIdx.x & 31;
    int c, t;
    if (g_is64) {
        c = (int)((const long long*)curp)[w];
        t = (int)((const long long*)tgtp)[w];
    } else {
        c = ((const int*)curp)[w];
        t = ((const int*)tgtp)[w];
    }
    float4 hv = ((const float4*)act)[(size_t)c * (DD / 4) + lane];
    float4 tv = ((const float4*)act)[(size_t)t * (DD / 4) + lane];
    float4 cv = __ldcs(((const float4*)cases) + (size_t)w * (DD / 4) + lane);
    float dx = hv.x + cv.x - tv.x;
    float dy = hv.y + cv.y - tv.y;
    float dz = hv.z + cv.z - tv.z;
    float dw = hv.w + cv.w - tv.w;
    float s = dx * dx + dy * dy + dz * dz + dw * dw;
#pragma unroll
    for (int o = 16; o; o >>= 1) s += __shfl_xor_sync(0xffffffffu, s, o);
    if (lane == 0) {
        float v = __expf(-sqrtf(s));
        atomicAdd(&g_att[(size_t)t * NN + c], v);
        atomicAdd(&g_norm[t], v);
    }
}

// ---------------------------------------------------------------------------
// tf32 helpers
// ---------------------------------------------------------------------------
__device__ __forceinline__ unsigned f2tf(float x) {
    unsigned r;
    asm("cvt.rna.tf32.f32 %0, %1;" : "=r"(r) : "f"(x));
    return r;
}

// ---------------------------------------------------------------------------
// Kernel 2: elementwise tf32-round source -> g_Bcvt (SAME layout).
// Source selected DEVICE-SIDE: use_feat ? g_feat : Xin. Optionally writes
// source verbatim to outc (fuses the "out = feat" pre-init for GEMM2).
// ---------------------------------------------------------------------------
__global__ void k_prepB(const float* __restrict__ Xin, int use_feat,
                        float* __restrict__ outc) {
    const float* X = use_feat ? g_feat : Xin;
    int idx = blockIdx.x * blockDim.x + threadIdx.x;   // 0 .. 131071
    float4 v = ((const float4*)X)[idx];
    float4 r;
    r.x = __uint_as_float(f2tf(v.x));
    r.y = __uint_as_float(f2tf(v.y));
    r.z = __uint_as_float(f2tf(v.z));
    r.w = __uint_as_float(f2tf(v.w));
    ((float4*)g_Bcvt)[idx] = r;
    if (outc) ((float4*)outc)[idx] = v;
}

__device__ __forceinline__ void mma8(float* c, unsigned a0, unsigned a1,
                                     unsigned a2, unsigned a3,
                                     unsigned b0, unsigned b1) {
    asm volatile(
        "mma.sync.aligned.m16n8k8.row.col.f32.tf32.tf32.f32 "
        "{%0,%1,%2,%3}, {%4,%5,%6,%7}, {%8,%9}, {%0,%1,%2,%3};"
        : "+f"(c[0]), "+f"(c[1]), "+f"(c[2]), "+f"(c[3])
        : "r"(a0), "r"(a1), "r"(a2), "r"(a3), "r"(b0), "r"(b1));
}

__device__ __forceinline__ void cp16(float* smem_dst, const float* gmem_src) {
    unsigned sa = (unsigned)__cvta_generic_to_shared(smem_dst);
    asm volatile("cp.async.cg.shared.global [%0], [%1], 16;" :: "r"(sa), "l"(gmem_src));
}

// ---------------------------------------------------------------------------
// Kernel 4: tensor-core GEMM  C[4096,128] = A[4096,4096] @ B[4096,128]
// 4-stage cp.async pipeline (prefetch distance 3 hides DRAM latency — R12
// profile showed tensor=33%/occ=19.5%: latency-exposed, not issue-bound).
// Zero in-loop cvt: B pre-rounded tf32 in g_Bcvt; A raw fp32 bits (tf32 HMMA
// reads upper 19 bits — truncation, random-sign error, aggregate ~5e-4).
// Always-commit group accounting: wait_group 3 => tile `it` retired.
//   mode 0: A=W,     B=g_Bcvt(=tf32(act)),  C=g_feat (zeroed)
//   mode 1: A=g_att, B=g_Bcvt(=tf32(feat)), C=out (holds feat), 1/(norm+eps)
// ---------------------------------------------------------------------------
__global__ void __launch_bounds__(256, 2)
k_gemm_tc(const float* __restrict__ Wp, float* __restrict__ outp, int mode) {
    extern __shared__ __align__(16) float smdyn[];
    float* AsBase = smdyn;                           // STAGES x AS_FLOATS
    float* BsBase = smdyn + STAGES * AS_FLOATS;      // STAGES x BS_FLOATS

    const float* A = mode ? g_att : Wp;
    const float* B = g_Bcvt;
    float* C       = mode ? outp  : g_feat;

    const int tid  = threadIdx.x;
    const int lane = tid & 31;
    const int w    = tid >> 5;
    const int wm   = w & 3;      // warp row group (0..3) -> rows wm*32..+32
    const int wn   = w >> 2;     // warp col group (0..1) -> cols wn*64..+64
    const int m0   = blockIdx.x * BM;
    const int k0   = blockIdx.y * (NN / KS);
    const int NT   = (NN / KS) / BK;  // 32 k-tiles

    float acc[2][8][4];
#pragma unroll
    for (int t = 0; t < 2; t++)
#pragma unroll
        for (int j = 0; j < 8; j++)
#pragma unroll
            for (int q = 0; q < 4; q++) acc[t][j][q] = 0.f;

    // ---- tile loader (cp.async, 4 x 16B per thread; commit done by caller) ----
    auto load_tile = [&](int st, int kt) {
        float* As = AsBase + st * AS_FLOATS;
        float* Bs = BsBase + st * BS_FLOATS;
#pragma unroll
        for (int s = 0; s < 2; s++) {
            int chunk = tid + 256 * s;              // 0..511
            int row = chunk >> 2, kq = chunk & 3;   // A: 128 rows x 4 float4
            cp16(&As[row * AS_STRIDE + kq * 4],
                 A + (size_t)(m0 + row) * NN + kt + kq * 4);
        }
#pragma unroll
        for (int s = 0; s < 2; s++) {
            int chunk = tid + 256 * s;
            int kr = chunk >> 5, nq = chunk & 31;   // B: 16 rows x 32 float4
            cp16(&Bs[kr * BS_STRIDE + nq * 4],
                 B + (size_t)(kt + kr) * DD + nq * 4);
        }
    };

    // prologue: tiles 0..2 into stages 0..2 (3 committed groups)
#pragma unroll
    for (int p = 0; p < STAGES - 1; p++) {
        load_tile(p, k0 + p * BK);
        asm volatile("cp.async.commit_group;");
    }

    for (int it = 0; it < NT; it++) {
        const int st = it & (STAGES - 1);
        if (it + STAGES - 1 < NT)
            load_tile((it + STAGES - 1) & (STAGES - 1), k0 + (it + STAGES - 1) * BK);
        asm volatile("cp.async.commit_group;");      // always (empty at tail)
        asm volatile("cp.async.wait_group %0;" :: "n"(STAGES - 1));
        __syncthreads();

        const float* As = AsBase + st * AS_FLOATS;
        const float* Bs = BsBase + st * BS_FLOATS;
#pragma unroll
        for (int ks = 0; ks < BK; ks += 8) {
            // A fragments (m16k8): raw fp32 bits, HW truncates to tf32
            unsigned ah[2][4];
#pragma unroll
            for (int t = 0; t < 2; t++) {
                int r = wm * 32 + t * 16 + (lane >> 2);
                int c = ks + (lane & 3);
                ah[t][0] = __float_as_uint(As[r * AS_STRIDE + c]);
                ah[t][1] = __float_as_uint(As[(r + 8) * AS_STRIDE + c]);
                ah[t][2] = __float_as_uint(As[r * AS_STRIDE + c + 4]);
                ah[t][3] = __float_as_uint(As[(r + 8) * AS_STRIDE + c + 4]);
            }
#pragma unroll
            for (int jb = 0; jb < 2; jb++) {
                unsigned bh[4][2];
#pragma unroll
                for (int jj = 0; jj < 4; jj++) {
                    int j = jb * 4 + jj;
                    int kk = ks + (lane & 3);
                    int n  = wn * 64 + j * 8 + (lane >> 2);
                    bh[jj][0] = __float_as_uint(Bs[kk * BS_STRIDE + n]);
                    bh[jj][1] = __float_as_uint(Bs[(kk + 4) * BS_STRIDE + n]);
                }
#pragma unroll
                for (int t = 0; t < 2; t++)
#pragma unroll
                    for (int jj = 0; jj < 4; jj++) {
                        mma8(acc[t][jb * 4 + jj], ah[t][0], ah[t][1], ah[t][2],
                             ah[t][3], bh[jj][0], bh[jj][1]);
                    }
            }
        }
        __syncthreads();   // protect stage st from next iteration's overwrite
    }

    // ---- epilogue: split-K atomic accumulate (mode1 scales by 1/(norm+eps)) ----
#pragma unroll
    for (int t = 0; t < 2; t++) {
        int r0 = m0 + wm * 32 + t * 16 + (lane >> 2);
        float inv0 = 1.f, inv1 = 1.f;
        if (mode) {
            inv0 = 1.f / (g_norm[r0] + EPSF);
            inv1 = 1.f / (g_norm[r0 + 8] + EPSF);
        }
#pragma unroll
        for (int j = 0; j < 8; j++) {
            int cc = wn * 64 + j * 8 + (lane & 3) * 2;
            atomicAdd(&C[(size_t)r0 * DD + cc],           inv0 * acc[t][j][0]);
            atomicAdd(&C[(size_t)r0 * DD + cc + 1],       inv0 * acc[t][j][1]);
            atomicAdd(&C[(size_t)(r0 + 8) * DD + cc],     inv1 * acc[t][j][2]);
            atomicAdd(&C[(size_t)(r0 + 8) * DD + cc + 1], inv1 * acc[t][j][3]);
        }
    }
}

// ---------------------------------------------------------------------------
extern "C" void kernel_launch(void* const* d_in, const int* in_sizes, int n_in,
                              void* d_out, int out_size) {
    const void*  cur   = d_in[0];                 // currents (int64 or int32), [E]
    const void*  tgt   = d_in[1];                 // targets, [E]
    const float* act   = (const float*)d_in[2];   // activities_features [N, D]
    const float* cases = (const float*)d_in[3];   // cases_features [E, D]
    const float* W     = (const float*)d_in[4];   // W [N, N]
    float* out = (float*)d_out;                   // h [N, D]

    int E = in_sizes[3] / DD;                     // unambiguous regardless of index dtype

    cudaFuncSetAttribute(k_gemm_tc, cudaFuncAttributeMaxDynamicSharedMemorySize,
                         SMEM_BYTES);

    // 0) zero scratch + dtype sniff
    k_zero<<<4096, 256>>>((const unsigned*)cur);
    // 1) g_Bcvt = tf32(activities)
    k_prepB<<<512, 256>>>(act, 0, nullptr);
    // 2) edge scatter into dense att + row norms
    k_edge<<<(E + 7) / 8, 256>>>(cur, tgt, act, cases, E);
    // 3) feat = W @ activities (split-K accumulate into zeroed g_feat)
    k_gemm_tc<<<dim3(NN / BM, KS), 256, SMEM_BYTES>>>(W, out, 0);
    // 4) g_Bcvt = tf32(feat) and out = feat (device-side source select)
    k_prepB<<<512, 256>>>(nullptr, 1, out);
    // 5) out += (att @ feat) / (norm + eps)
    k_gemm_tc<<<dim3(NN / BM, KS), 256, SMEM_BYTES>>>(W, out, 1);
}

// round 14
// speedup vs baseline: 1.4200x; 1.4200x over previous
#include <cuda_runtime.h>
#include <cstdint>

#define NN 4096
#define DD 128
#define EPSF 1e-12f
#define KS 8            // split-K factor for GEMMs (256 CTAs -> 2/SM)
#define BM 128          // GEMM block rows
#define BK 16           // GEMM k-tile
#define AS_STRIDE 20    // floats; conflict-free for As[m][k] frag reads
#define BS_STRIDE 136   // floats; conflict-free for Bs[k][n] frag reads

// Scratch (static device allocation — no cudaMalloc allowed).
// RULE: __device__ symbols are NEVER passed as kernel args from host code.
__device__ __align__(256) float g_att[(size_t)NN * NN];  // 64 MB dense att input
__device__ __align__(256) float g_feat[NN * DD];         // W @ activities (raw fp32)
__device__ __align__(256) float g_Bcvt[NN * DD];         // current B, tf32-rounded
__device__ __align__(256) float g_norm[NN];              // row sums of g_att
__device__ int g_is64;                                   // index dtype sniff

// ---------------------------------------------------------------------------
// Kernel 0: zero att + norm, sniff int64 vs int32 indices.
// (g_feat zeroing moved to k_prepB so it lives on the GEMM1 stream.)
// ---------------------------------------------------------------------------
__global__ void k_zero(const unsigned* __restrict__ cur_raw) {
    if (blockIdx.x == 0 && threadIdx.x == 0) {
        unsigned o = 0;
#pragma unroll
        for (int i = 1; i < 128; i += 2) o |= cur_raw[i];
        g_is64 = (o == 0) ? 1 : 0;
    }
    size_t idx    = (size_t)blockIdx.x * blockDim.x + threadIdx.x;
    size_t stride = (size_t)gridDim.x * blockDim.x;
    float4 z = make_float4(0.f, 0.f, 0.f, 0.f);
    float4* pa = (float4*)g_att;
    const size_t na = ((size_t)NN * NN) / 4;
    for (size_t i = idx; i < na; i += stride) pa[i] = z;
    for (size_t i = idx; i < NN; i += stride) g_norm[i] = 0.f;
}

// ---------------------------------------------------------------------------
// Kernel 1: one warp per edge. dist = ||h + case - t||, val = exp(-dist),
// scatter into att[t][c] and accumulate row norm (linear => == row sums).
// ---------------------------------------------------------------------------
__global__ void k_edge(const void* __restrict__ curp, const void* __restrict__ tgtp,
                       const float* __restrict__ act, const float* __restrict__ cases,
                       int E) {
    int w = (int)((blockIdx.x * blockDim.x + threadIdx.x) >> 5);
    if (w >= E) return;
    int lane = threadIdx.x & 31;
    int c, t;
    if (g_is64) {
        c = (int)((const long long*)curp)[w];
        t = (int)((const long long*)tgtp)[w];
    } else {
        c = ((const int*)curp)[w];
        t = ((const int*)tgtp)[w];
    }
    float4 hv = ((const float4*)act)[(size_t)c * (DD / 4) + lane];
    float4 tv = ((const float4*)act)[(size_t)t * (DD / 4) + lane];
    float4 cv = __ldcs(((const float4*)cases) + (size_t)w * (DD / 4) + lane);
    float dx = hv.x + cv.x - tv.x;
    float dy = hv.y + cv.y - tv.y;
    float dz = hv.z + cv.z - tv.z;
    float dw = hv.w + cv.w - tv.w;
    float s = dx * dx + dy * dy + dz * dz + dw * dw;
#pragma unroll
    for (int o = 16; o; o >>= 1) s += __shfl_xor_sync(0xffffffffu, s, o);
    if (lane == 0) {
        float v = __expf(-sqrtf(s));
        atomicAdd(&g_att[(size_t)t * NN + c], v);
        atomicAdd(&g_norm[t], v);
    }
}

// ---------------------------------------------------------------------------
// tf32 helpers
// ---------------------------------------------------------------------------
__device__ __forceinline__ unsigned f2tf(float x) {
    unsigned r;
    asm("cvt.rna.tf32.f32 %0, %1;" : "=r"(r) : "f"(x));
    return r;
}

// ---------------------------------------------------------------------------
// Kernel 2: elementwise tf32-round source -> g_Bcvt (SAME layout).
// Source selected DEVICE-SIDE: use_feat ? g_feat : Xin. Optional extras:
//   outc != null  -> write source verbatim to outc ("out = feat" pre-init)
//   zero_feat     -> also zero g_feat (pre-init for GEMM1's atomic epilogue)
// ---------------------------------------------------------------------------
__global__ void k_prepB(const float* __restrict__ Xin, int use_feat,
                        float* __restrict__ outc, int zero_feat) {
    const float* X = use_feat ? g_feat : Xin;
    int idx = blockIdx.x * blockDim.x + threadIdx.x;   // 0 .. 131071
    float4 v = ((const float4*)X)[idx];
    float4 r;
    r.x = __uint_as_float(f2tf(v.x));
    r.y = __uint_as_float(f2tf(v.y));
    r.z = __uint_as_float(f2tf(v.z));
    r.w = __uint_as_float(f2tf(v.w));
    ((float4*)g_Bcvt)[idx] = r;
    if (outc) ((float4*)outc)[idx] = v;
    if (zero_feat) ((float4*)g_feat)[idx] = make_float4(0.f, 0.f, 0.f, 0.f);
}

__device__ __forceinline__ void mma8(float* c, unsigned a0, unsigned a1,
                                     unsigned a2, unsigned a3,
                                     unsigned b0, unsigned b1) {
    asm volatile(
        "mma.sync.aligned.m16n8k8.row.col.f32.tf32.tf32.f32 "
        "{%0,%1,%2,%3}, {%4,%5,%6,%7}, {%8,%9}, {%0,%1,%2,%3};"
        : "+f"(c[0]), "+f"(c[1]), "+f"(c[2]), "+f"(c[3])
        : "r"(a0), "r"(a1), "r"(a2), "r"(a3), "r"(b0), "r"(b1));
}

__device__ __forceinline__ void cp16(float* smem_dst, const float* gmem_src) {
    unsigned sa = (unsigned)__cvta_generic_to_shared(smem_dst);
    asm volatile("cp.async.cg.shared.global [%0], [%1], 16;" :: "r"(sa), "l"(gmem_src));
}

// ---------------------------------------------------------------------------
// Kernel 4: tensor-core GEMM — EXACT R12 version (proven 42us/launch).
// B pre-rounded tf32 (g_Bcvt); A fragments cvt.rna in-loop. Double-buffered
// cp.async BK=16 tiles, split-K=8 atomic epilogue, 2 CTAs/SM.
//   mode 0: A=W,     B=g_Bcvt(=tf32(act)),  C=g_feat (zeroed)
//   mode 1: A=g_att, B=g_Bcvt(=tf32(feat)), C=out (holds feat), 1/(norm+eps)
// ---------------------------------------------------------------------------
__global__ void __launch_bounds__(256, 2)
k_gemm_tc(const float* __restrict__ Wp, float* __restrict__ outp, int mode) {
    __shared__ __align__(16) float As[2][BM * AS_STRIDE];  // 20480 B
    __shared__ __align__(16) float Bs[2][BK * BS_STRIDE];  // 17408 B

    const float* A = mode ? g_att : Wp;
    const float* B = g_Bcvt;
    float* C       = mode ? outp  : g_feat;

    const int tid  = threadIdx.x;
    const int lane = tid & 31;
    const int w    = tid >> 5;
    const int wm   = w & 3;      // warp row group (0..3) -> rows wm*32..+32
    const int wn   = w >> 2;     // warp col group (0..1) -> cols wn*64..+64
    const int m0   = blockIdx.x * BM;
    const int k0   = blockIdx.y * (NN / KS);
    const int NT   = (NN / KS) / BK;  // 32 k-tiles

    float acc[2][8][4];
#pragma unroll
    for (int t = 0; t < 2; t++)
#pragma unroll
        for (int j = 0; j < 8; j++)
#pragma unroll
            for (int q = 0; q < 4; q++) acc[t][j][q] = 0.f;

    // ---- tile loader (cp.async, 4 x 16B per thread) ----
    auto load_tile = [&](int buf, int kt) {
#pragma unroll
        for (int s = 0; s < 2; s++) {
            int chunk = tid + 256 * s;              // 0..511
            int row = chunk >> 2, kq = chunk & 3;   // A: 128 rows x 4 float4
            cp16(&As[buf][row * AS_STRIDE + kq * 4],
                 A + (size_t)(m0 + row) * NN + kt + kq * 4);
        }
#pragma unroll
        for (int s = 0; s < 2; s++) {
            int chunk = tid + 256 * s;
            int kr = chunk >> 5, nq = chunk & 31;   // B: 16 rows x 32 float4
            cp16(&Bs[buf][kr * BS_STRIDE + nq * 4],
                 B + (size_t)(kt + kr) * DD + nq * 4);
        }
        asm volatile("cp.async.commit_group;");
    };

    load_tile(0, k0);

    for (int it = 0; it < NT; it++) {
        int buf = it & 1;
        if (it + 1 < NT) {
            load_tile(buf ^ 1, k0 + (it + 1) * BK);
            asm volatile("cp.async.wait_group 1;");
        } else {
            asm volatile("cp.async.wait_group 0;");
        }
        __syncthreads();

#pragma unroll
        for (int ks = 0; ks < BK; ks += 8) {
            // A fragments (m16k8), tf32-converted (rna)
            unsigned ah[2][4];
#pragma unroll
            for (int t = 0; t < 2; t++) {
                int r = wm * 32 + t * 16 + (lane >> 2);
                int c = ks + (lane & 3);
                ah[t][0] = f2tf(As[buf][r * AS_STRIDE + c]);
                ah[t][1] = f2tf(As[buf][(r + 8) * AS_STRIDE + c]);
                ah[t][2] = f2tf(As[buf][r * AS_STRIDE + c + 4]);
                ah[t][3] = f2tf(As[buf][(r + 8) * AS_STRIDE + c + 4]);
            }
#pragma unroll
            for (int jb = 0; jb < 2; jb++) {
                unsigned bh[4][2];
#pragma unroll
                for (int jj = 0; jj < 4; jj++) {
                    int j = jb * 4 + jj;
                    int kk = ks + (lane & 3);
                    int n  = wn * 64 + j * 8 + (lane >> 2);
                    bh[jj][0] = __float_as_uint(Bs[buf][kk * BS_STRIDE + n]);
                    bh[jj][1] = __float_as_uint(Bs[buf][(kk + 4) * BS_STRIDE + n]);
                }
#pragma unroll
                for (int t = 0; t < 2; t++)
#pragma unroll
                    for (int jj = 0; jj < 4; jj++) {
                        mma8(acc[t][jb * 4 + jj], ah[t][0], ah[t][1], ah[t][2],
                             ah[t][3], bh[jj][0], bh[jj][1]);
                    }
            }
        }
        __syncthreads();
    }

    // ---- epilogue: split-K atomic accumulate (mode1 scales by 1/(norm+eps)) ----
#pragma unroll
    for (int t = 0; t < 2; t++) {
        int r0 = m0 + wm * 32 + t * 16 + (lane >> 2);
        float inv0 = 1.f, inv1 = 1.f;
        if (mode) {
            inv0 = 1.f / (g_norm[r0] + EPSF);
            inv1 = 1.f / (g_norm[r0 + 8] + EPSF);
        }
#pragma unroll
        for (int j = 0; j < 8; j++) {
            int cc = wn * 64 + j * 8 + (lane & 3) * 2;
            atomicAdd(&C[(size_t)r0 * DD + cc],           inv0 * acc[t][j][0]);
            atomicAdd(&C[(size_t)r0 * DD + cc + 1],       inv0 * acc[t][j][1]);
            atomicAdd(&C[(size_t)(r0 + 8) * DD + cc],     inv1 * acc[t][j][2]);
            atomicAdd(&C[(size_t)(r0 + 8) * DD + cc + 1], inv1 * acc[t][j][3]);
        }
    }
}

// ---------------------------------------------------------------------------
// Launch: fork-join two streams so the memory-bound zero+edge phase (~170us)
// overlaps the tensor-bound prepB+GEMM1 phase (~48us). Standard event-based
// capture fork/join — becomes a branching graph. No device allocations.
// ---------------------------------------------------------------------------
extern "C" void kernel_launch(void* const* d_in, const int* in_sizes, int n_in,
                              void* d_out, int out_size) {
    const void*  cur   = d_in[0];                 // currents (int64 or int32), [E]
    const void*  tgt   = d_in[1];                 // targets, [E]
    const float* act   = (const float*)d_in[2];   // activities_features [N, D]
    const float* cases = (const float*)d_in[3];   // cases_features [E, D]
    const float* W     = (const float*)d_in[4];   // W [N, N]
    float* out = (float*)d_out;                   // h [N, D]

    int E = in_sizes[3] / DD;                     // unambiguous regardless of index dtype

    static cudaStream_t s2 = nullptr;
    static cudaEvent_t evFork = nullptr, evJoin = nullptr;
    if (!s2) {
        cudaStreamCreateWithFlags(&s2, cudaStreamNonBlocking);
        cudaEventCreateWithFlags(&evFork, cudaEventDisableTiming);
        cudaEventCreateWithFlags(&evJoin, cudaEventDisableTiming);
    }

    // ---- fork: branch B is independent of branch A until the join ----
    cudaEventRecord(evFork, 0);
    cudaStreamWaitEvent(s2, evFork, 0);

    // Branch B (stream s2): g_Bcvt = tf32(act), zero g_feat, then GEMM1
    k_prepB<<<512, 256, 0, s2>>>(act, 0, nullptr, 1);
    k_gemm_tc<<<dim3(NN / BM, KS), 256, 0, s2>>>(W, nullptr, 0);
    cudaEventRecord(evJoin, s2);

    // Branch A (default stream): zero att+norm, edge scatter
    k_zero<<<4096, 256>>>((const unsigned*)cur);
    k_edge<<<(E + 7) / 8, 256>>>(cur, tgt, act, cases, E);

    // ---- join ----
    cudaStreamWaitEvent(0, evJoin, 0);

    // g_Bcvt = tf32(feat) and out = feat (device-side source select)
    k_prepB<<<512, 256>>>(nullptr, 1, out, 0);
    // out += (att @ feat) / (norm + eps)
    k_gemm_tc<<<dim3(NN / BM, KS), 256>>>(W, out, 1);
}

// round 15
// speedup vs baseline: 1.9072x; 1.3430x over previous
#include <cuda_runtime.h>
#include <cstdint>

#define NN 4096
#define DD 128
#define EPSF 1e-12f
#define KS 8            // split-K factor for GEMMs (256 CTAs -> 2/SM)
#define BM 128          // GEMM block rows
#define BK 16           // GEMM k-tile
#define AS_STRIDE 20    // floats; conflict-free for As[m][k] frag reads
#define BS_STRIDE 136   // floats; conflict-free for Bs[k][n] frag reads

// Scratch (static device allocation — no cudaMalloc allowed).
// RULE: __device__ symbols are NEVER passed as kernel args from host code.
__device__ __align__(256) float g_att[(size_t)NN * NN];  // 64 MB dense att input
__device__ __align__(256) float g_feat[NN * DD];         // W @ activities (raw fp32)
__device__ __align__(256) float g_Bcvt[NN * DD];         // current B, tf32-rounded
__device__ __align__(256) float g_norm[NN];              // row sums of g_att
__device__ int g_is64;                                   // index dtype sniff

// ---------------------------------------------------------------------------
// Kernel 0: zero att + norm, sniff int64 vs int32 indices.
// (g_feat zeroing lives in k_prepB on the GEMM1 stream.)
// ---------------------------------------------------------------------------
__global__ void k_zero(const unsigned* __restrict__ cur_raw) {
    if (blockIdx.x == 0 && threadIdx.x == 0) {
        unsigned o = 0;
#pragma unroll
        for (int i = 1; i < 128; i += 2) o |= cur_raw[i];
        g_is64 = (o == 0) ? 1 : 0;
    }
    size_t idx    = (size_t)blockIdx.x * blockDim.x + threadIdx.x;
    size_t stride = (size_t)gridDim.x * blockDim.x;
    float4 z = make_float4(0.f, 0.f, 0.f, 0.f);
    float4* pa = (float4*)g_att;
    const size_t na = ((size_t)NN * NN) / 4;
    for (size_t i = idx; i < na; i += stride) pa[i] = z;
    for (size_t i = idx; i < NN; i += stride) g_norm[i] = 0.f;
}

// ---------------------------------------------------------------------------
// Kernel 1: 4 edges per warp, 8 lanes per edge, 4 float4-chunks per lane.
// 12 outstanding LDG.128 per lane (MLP=12) instead of 3; 3-shfl butterfly
// covers all 4 edges at once; att/norm atomics issued by separate lanes.
// dist = ||h + case - t||, val = exp(-dist); scatter att[t][c], norm[t].
// ---------------------------------------------------------------------------
__global__ void k_edge(const void* __restrict__ curp, const void* __restrict__ tgtp,
                       const float* __restrict__ act, const float* __restrict__ cases,
                       int E) {
    int wid  = (int)((blockIdx.x * blockDim.x + threadIdx.x) >> 5);
    int lane = threadIdx.x & 31;
    int g    = lane >> 3;      // edge slot within warp (0..3)
    int sub  = lane & 7;       // lane within edge group
    int e    = wid * 4 + g;
    if (e >= E) return;

    int c, t;
    if (g_is64) {
        c = (int)((const long long*)curp)[e];
        t = (int)((const long long*)tgtp)[e];
    } else {
        c = ((const int*)curp)[e];
        t = ((const int*)tgtp)[e];
    }

    const float4* ha = (const float4*)act   + (size_t)c * (DD / 4) + sub;
    const float4* ta = (const float4*)act   + (size_t)t * (DD / 4) + sub;
    const float4* ca = (const float4*)cases + (size_t)e * (DD / 4) + sub;

    float4 hv[4], tv[4], cv[4];
#pragma unroll
    for (int i = 0; i < 4; i++) {           // 12 LDGs issued back-to-back
        hv[i] = ha[i * 8];
        tv[i] = ta[i * 8];
        cv[i] = __ldcs(ca + i * 8);
    }

    float s = 0.f;
#pragma unroll
    for (int i = 0; i < 4; i++) {
        float dx = hv[i].x + cv[i].x - tv[i].x;
        float dy = hv[i].y + cv[i].y - tv[i].y;
        float dz = hv[i].z + cv[i].z - tv[i].z;
        float dw = hv[i].w + cv[i].w - tv[i].w;
        s = fmaf(dx, dx, s);
        s = fmaf(dy, dy, s);
        s = fmaf(dz, dz, s);
        s = fmaf(dw, dw, s);
    }
    // butterfly within the 8-lane group (covers all 4 edges simultaneously)
    s += __shfl_xor_sync(0xffffffffu, s, 1);
    s += __shfl_xor_sync(0xffffffffu, s, 2);
    s += __shfl_xor_sync(0xffffffffu, s, 4);

    float v = __expf(-sqrtf(s));
    if (sub == 0) atomicAdd(&g_att[(size_t)t * NN + c], v);
    if (sub == 1) atomicAdd(&g_norm[t], v);
}

// ---------------------------------------------------------------------------
// tf32 helpers
// ---------------------------------------------------------------------------
__device__ __forceinline__ unsigned f2tf(float x) {
    unsigned r;
    asm("cvt.rna.tf32.f32 %0, %1;" : "=r"(r) : "f"(x));
    return r;
}

// ---------------------------------------------------------------------------
// Kernel 2: elementwise tf32-round source -> g_Bcvt (SAME layout).
// Source selected DEVICE-SIDE: use_feat ? g_feat : Xin. Optional extras:
//   outc != null  -> write source verbatim to outc ("out = feat" pre-init)
//   zero_feat     -> also zero g_feat (pre-init for GEMM1's atomic epilogue)
// ---------------------------------------------------------------------------
__global__ void k_prepB(const float* __restrict__ Xin, int use_feat,
                        float* __restrict__ outc, int zero_feat) {
    const float* X = use_feat ? g_feat : Xin;
    int idx = blockIdx.x * blockDim.x + threadIdx.x;   // 0 .. 131071
    float4 v = ((const float4*)X)[idx];
    float4 r;
    r.x = __uint_as_float(f2tf(v.x));
    r.y = __uint_as_float(f2tf(v.y));
    r.z = __uint_as_float(f2tf(v.z));
    r.w = __uint_as_float(f2tf(v.w));
    ((float4*)g_Bcvt)[idx] = r;
    if (outc) ((float4*)outc)[idx] = v;
    if (zero_feat) ((float4*)g_feat)[idx] = make_float4(0.f, 0.f, 0.f, 0.f);
}

__device__ __forceinline__ void mma8(float* c, unsigned a0, unsigned a1,
                                     unsigned a2, unsigned a3,
                                     unsigned b0, unsigned b1) {
    asm volatile(
        "mma.sync.aligned.m16n8k8.row.col.f32.tf32.tf32.f32 "
        "{%0,%1,%2,%3}, {%4,%5,%6,%7}, {%8,%9}, {%0,%1,%2,%3};"
        : "+f"(c[0]), "+f"(c[1]), "+f"(c[2]), "+f"(c[3])
        : "r"(a0), "r"(a1), "r"(a2), "r"(a3), "r"(b0), "r"(b1));
}

__device__ __forceinline__ void cp16(float* smem_dst, const float* gmem_src) {
    unsigned sa = (unsigned)__cvta_generic_to_shared(smem_dst);
    asm volatile("cp.async.cg.shared.global [%0], [%1], 16;" :: "r"(sa), "l"(gmem_src));
}

// ---------------------------------------------------------------------------
// Kernel 4: tensor-core GEMM — proven R12/R14 version (42us/launch).
// B pre-rounded tf32 (g_Bcvt); A fragments cvt.rna in-loop. Double-buffered
// cp.async BK=16 tiles, split-K=8 atomic epilogue, 2 CTAs/SM.
//   mode 0: A=W,     B=g_Bcvt(=tf32(act)),  C=g_feat (zeroed)
//   mode 1: A=g_att, B=g_Bcvt(=tf32(feat)), C=out (holds feat), 1/(norm+eps)
// ---------------------------------------------------------------------------
__global__ void __launch_bounds__(256, 2)
k_gemm_tc(const float* __restrict__ Wp, float* __restrict__ outp, int mode) {
    __shared__ __align__(16) float As[2][BM * AS_STRIDE];  // 20480 B
    __shared__ __align__(16) float Bs[2][BK * BS_STRIDE];  // 17408 B

    const float* A = mode ? g_att : Wp;
    const float* B = g_Bcvt;
    float* C       = mode ? outp  : g_feat;

    const int tid  = threadIdx.x;
    const int lane = tid & 31;
    const int w    = tid >> 5;
    const int wm   = w & 3;      // warp row group (0..3) -> rows wm*32..+32
    const int wn   = w >> 2;     // warp col group (0..1) -> cols wn*64..+64
    const int m0   = blockIdx.x * BM;
    const int k0   = blockIdx.y * (NN / KS);
    const int NT   = (NN / KS) / BK;  // 32 k-tiles

    float acc[2][8][4];
#pragma unroll
    for (int t = 0; t < 2; t++)
#pragma unroll
        for (int j = 0; j < 8; j++)
#pragma unroll
            for (int q = 0; q < 4; q++) acc[t][j][q] = 0.f;

    // ---- tile loader (cp.async, 4 x 16B per thread) ----
    auto load_tile = [&](int buf, int kt) {
#pragma unroll
        for (int s = 0; s < 2; s++) {
            int chunk = tid + 256 * s;              // 0..511
            int row = chunk >> 2, kq = chunk & 3;   // A: 128 rows x 4 float4
            cp16(&As[buf][row * AS_STRIDE + kq * 4],
                 A + (size_t)(m0 + row) * NN + kt + kq * 4);
        }
#pragma unroll
        for (int s = 0; s < 2; s++) {
            int chunk = tid + 256 * s;
            int kr = chunk >> 5, nq = chunk & 31;   // B: 16 rows x 32 float4
            cp16(&Bs[buf][kr * BS_STRIDE + nq * 4],
                 B + (size_t)(kt + kr) * DD + nq * 4);
        }
        asm volatile("cp.async.commit_group;");
    };

    load_tile(0, k0);

    for (int it = 0; it < NT; it++) {
        int buf = it & 1;
        if (it + 1 < NT) {
            load_tile(buf ^ 1, k0 + (it + 1) * BK);
            asm volatile("cp.async.wait_group 1;");
        } else {
            asm volatile("cp.async.wait_group 0;");
        }
        __syncthreads();

#pragma unroll
        for (int ks = 0; ks < BK; ks += 8) {
            // A fragments (m16k8), tf32-converted (rna)
            unsigned ah[2][4];
#pragma unroll
            for (int t = 0; t < 2; t++) {
                int r = wm * 32 + t * 16 + (lane >> 2);
                int c = ks + (lane & 3);
                ah[t][0] = f2tf(As[buf][r * AS_STRIDE + c]);
                ah[t][1] = f2tf(As[buf][(r + 8) * AS_STRIDE + c]);
                ah[t][2] = f2tf(As[buf][r * AS_STRIDE + c + 4]);
                ah[t][3] = f2tf(As[buf][(r + 8) * AS_STRIDE + c + 4]);
            }
#pragma unroll
            for (int jb = 0; jb < 2; jb++) {
                unsigned bh[4][2];
#pragma unroll
                for (int jj = 0; jj < 4; jj++) {
                    int j = jb * 4 + jj;
                    int kk = ks + (lane & 3);
                    int n  = wn * 64 + j * 8 + (lane >> 2);
                    bh[jj][0] = __float_as_uint(Bs[buf][kk * BS_STRIDE + n]);
                    bh[jj][1] = __float_as_uint(Bs[buf][(kk + 4) * BS_STRIDE + n]);
                }
#pragma unroll
                for (int t = 0; t < 2; t++)
#pragma unroll
                    for (int jj = 0; jj < 4; jj++) {
                        mma8(acc[t][jb * 4 + jj], ah[t][0], ah[t][1], ah[t][2],
                             ah[t][3], bh[jj][0], bh[jj][1]);
                    }
            }
        }
        __syncthreads();
    }

    // ---- epilogue: split-K atomic accumulate (mode1 scales by 1/(norm+eps)) ----
#pragma unroll
    for (int t = 0; t < 2; t++) {
        int r0 = m0 + wm * 32 + t * 16 + (lane >> 2);
        float inv0 = 1.f, inv1 = 1.f;
        if (mode) {
            inv0 = 1.f / (g_norm[r0] + EPSF);
            inv1 = 1.f / (g_norm[r0 + 8] + EPSF);
        }
#pragma unroll
        for (int j = 0; j < 8; j++) {
            int cc = wn * 64 + j * 8 + (lane & 3) * 2;
            atomicAdd(&C[(size_t)r0 * DD + cc],           inv0 * acc[t][j][0]);
            atomicAdd(&C[(size_t)r0 * DD + cc + 1],       inv0 * acc[t][j][1]);
            atomicAdd(&C[(size_t)(r0 + 8) * DD + cc],     inv1 * acc[t][j][2]);
            atomicAdd(&C[(size_t)(r0 + 8) * DD + cc + 1], inv1 * acc[t][j][3]);
        }
    }
}

// ---------------------------------------------------------------------------
// Launch: fork-join two streams so the memory-bound zero+edge phase overlaps
// the tensor-bound prepB+GEMM1 phase. No device allocations.
// ---------------------------------------------------------------------------
extern "C" void kernel_launch(void* const* d_in, const int* in_sizes, int n_in,
                              void* d_out, int out_size) {
    const void*  cur   = d_in[0];                 // currents (int64 or int32), [E]
    const void*  tgt   = d_in[1];                 // targets, [E]
    const float* act   = (const float*)d_in[2];   // activities_features [N, D]
    const float* cases = (const float*)d_in[3];   // cases_features [E, D]
    const float* W     = (const float*)d_in[4];   // W [N, N]
    float* out = (float*)d_out;                   // h [N, D]

    int E = in_sizes[3] / DD;                     // unambiguous regardless of index dtype

    static cudaStream_t s2 = nullptr;
    static cudaEvent_t evFork = nullptr, evJoin = nullptr;
    if (!s2) {
        cudaStreamCreateWithFlags(&s2, cudaStreamNonBlocking);
        cudaEventCreateWithFlags(&evFork, cudaEventDisableTiming);
        cudaEventCreateWithFlags(&evJoin, cudaEventDisableTiming);
    }

    // ---- fork: branch B is independent of branch A until the join ----
    cudaEventRecord(evFork, 0);
    cudaStreamWaitEvent(s2, evFork, 0);

    // Branch B (stream s2): g_Bcvt = tf32(act), zero g_feat, then GEMM1
    k_prepB<<<512, 256, 0, s2>>>(act, 0, nullptr, 1);
    k_gemm_tc<<<dim3(NN / BM, KS), 256, 0, s2>>>(W, nullptr, 0);
    cudaEventRecord(evJoin, s2);

    // Branch A (default stream): zero att+norm, edge scatter (4 edges/warp)
    k_zero<<<4096, 256>>>((const unsigned*)cur);
    k_edge<<<((E / 4 + 7) / 8 + 0), 256>>>(cur, tgt, act, cases, E);

    // ---- join ----
    cudaStreamWaitEvent(0, evJoin, 0);

    // g_Bcvt = tf32(feat) and out = feat (device-side source select)
    k_prepB<<<512, 256>>>(nullptr, 1, out, 0);
    // out += (att @ feat) / (norm + eps)
    k_gemm_tc<<<dim3(NN / BM, KS), 256>>>(W, out, 1);
}